// round 4
// baseline (speedup 1.0000x reference)
#include <cuda_runtime.h>

#define NB   2
#define C    64
#define H    128
#define WW   128
#define HW   (H*WW)
#define NH   4
#define DK   16
#define KS   5
#define K2   25

// Scratch (allocation-free rule: __device__ globals).
// qp/kp/vp/mid stored pixel-major: [n, h*w, c]  (channel contiguous -> coalesced gathers)
__device__ float g_qp [NB*HW*C];
__device__ float g_kp [NB*HW*C];
__device__ float g_vp [NB*HW*C];
__device__ float g_mid[NB*HW*C];

// ---------------------------------------------------------------------------
// Kernel 1: three 1x1 convs, [n,c,h,w] -> [n,h*w,c] (transposed), register-tiled.
// Block: 256 threads, tile 128 pixels x 64 outs. Thread: 4 pix x 8 outs.
// ---------------------------------------------------------------------------
__global__ __launch_bounds__(256) void conv_in_kernel(
    const float* __restrict__ q,
    const float* __restrict__ k,
    const float* __restrict__ v,
    const float* __restrict__ Wq,
    const float* __restrict__ Wk,
    const float* __restrict__ Wv)
{
    __shared__ float Xs[64*128];

    const int which = blockIdx.y;
    const float* src = (which == 0) ? q  : (which == 1) ? k  : v;
    const float* Wsrc= (which == 0) ? Wq : (which == 1) ? Wk : Wv;
    float*       dst = (which == 0) ? g_qp : (which == 1) ? g_kp : g_vp;

    const int b       = blockIdx.x / (HW/128);
    const int pixBase = (blockIdx.x % (HW/128)) * 128;
    const int tid     = threadIdx.x;

    #pragma unroll
    for (int kx = 0; kx < 8; kx++) {
        int idx4 = tid + kx*256;
        int c  = idx4 >> 5;
        int p4 = idx4 & 31;
        float4 val = __ldg((const float4*)(src + (size_t)(b*C + c)*HW + pixBase + p4*4));
        *(float4*)&Xs[c*128 + p4*4] = val;
    }
    __syncthreads();

    const int tidx = tid & 31;
    const int tidy = tid >> 5;
    const float* Wb = Wsrc + tidy*8*C;

    float acc[4][8];
    #pragma unroll
    for (int j = 0; j < 4; j++)
        #pragma unroll
        for (int i = 0; i < 8; i++) acc[j][i] = 0.f;

    #pragma unroll 4
    for (int c0 = 0; c0 < 64; c0 += 4) {
        float wreg[8][4];
        #pragma unroll
        for (int i = 0; i < 8; i++) {
            float4 t = __ldg((const float4*)(Wb + i*C + c0));
            wreg[i][0] = t.x; wreg[i][1] = t.y; wreg[i][2] = t.z; wreg[i][3] = t.w;
        }
        #pragma unroll
        for (int cc = 0; cc < 4; cc++) {
            #pragma unroll
            for (int j = 0; j < 4; j++) {
                float xv = Xs[(c0+cc)*128 + tidx + 32*j];
                #pragma unroll
                for (int i = 0; i < 8; i++)
                    acc[j][i] = fmaf(wreg[i][cc], xv, acc[j][i]);
            }
        }
    }

    #pragma unroll
    for (int j = 0; j < 4; j++) {
        int pix = pixBase + tidx + 32*j;
        float4 a0 = make_float4(acc[j][0], acc[j][1], acc[j][2], acc[j][3]);
        float4 a1 = make_float4(acc[j][4], acc[j][5], acc[j][6], acc[j][7]);
        float* d = dst + (size_t)(b*HW + pix)*C + tidy*8;
        *(float4*)d       = a0;
        *(float4*)(d + 4) = a1;
    }
}

// ---------------------------------------------------------------------------
// Kernel 2: flow-guided attention, 6x6 shared-grid factorization, low-register.
// Warp per pixel. Rolling 2-row buffer for grid dots (no s[36]); coefficients
// recomputed in gather form in pass B (no cg[36]). Only p[25] persists.
// ---------------------------------------------------------------------------
__global__ __launch_bounds__(256) void attn_kernel(const float* __restrict__ flow,
                                                   float* __restrict__ attn_out)
{
    __shared__ float sP[8][NH][K2];
    __shared__ float sInv[8][NH];

    const int tid  = threadIdx.x;
    const int warp = tid >> 5;
    const int lane = tid & 31;

    const int b       = blockIdx.x / (HW/8);
    const int pixBase = (blockIdx.x % (HW/8)) * 8;
    const int pix     = pixBase + warp;
    const int y = pix >> 7;
    const int x = pix & 127;

    const float fx = flow[(b*2 + 0)*HW + pix];
    const float fy = flow[(b*2 + 1)*HW + pix];

    const float ax = (float)x + fx;
    const float ay = (float)y + fy;
    const float x0f = floorf(ax), y0f = floorf(ay);
    const int ix_base = (int)x0f - 2;
    const int iy_base = (int)y0f - 2;
    const float wx1 = ax - x0f, wx0 = 1.f - wx1;
    const float wy1 = ay - y0f, wy0 = 1.f - wy1;

    const float2* __restrict__ qp2 = (const float2*)g_qp;
    const float2* __restrict__ kp2 = (const float2*)g_kp;
    const float2* __restrict__ vp2 = (const float2*)g_vp;

    float2 qv = qp2[(size_t)(b*HW + pix)*32 + lane];
    const float scale = 0.25f;              // 1/sqrt(dk=16)
    qv.x *= scale; qv.y *= scale;

    const int head = lane >> 3;
    const size_t batchOff = (size_t)b*HW;

    // Rolling pass A: grid row dy -> srow[dy&1]; after row dy, emit logit row dy-1.
    float p[25];
    float m = -1e30f;
    float srow[2][6];

    #pragma unroll
    for (int dy = 0; dy < 6; dy++) {
        const int cur = dy & 1;
        int iy = iy_base + dy;
        bool okY = ((unsigned)iy < (unsigned)H);
        int iyc = min(max(iy, 0), H-1);
        #pragma unroll
        for (int dx = 0; dx < 6; dx++) {
            int ix = ix_base + dx;
            bool ok = okY && ((unsigned)ix < (unsigned)WW);
            int ixc = min(max(ix, 0), WW-1);
            float2 kv = __ldg(&kp2[(batchOff + iyc*WW + ixc)*32 + lane]);
            float d = qv.x*kv.x + qv.y*kv.y;
            d += __shfl_xor_sync(0xffffffffu, d, 1);
            d += __shfl_xor_sync(0xffffffffu, d, 2);
            d += __shfl_xor_sync(0xffffffffu, d, 4);
            srow[cur][dx] = ok ? d : 0.f;
        }
        if (dy > 0) {
            const int prv = cur ^ 1;
            #pragma unroll
            for (int tx = 0; tx < 5; tx++) {
                float l = wy0 * fmaf(wx0, srow[prv][tx], wx1 * srow[prv][tx+1])
                        + wy1 * fmaf(wx0, srow[cur][tx], wx1 * srow[cur][tx+1]);
                p[(dy-1)*5 + tx] = l;
                m = fmaxf(m, l);
            }
        }
    }

    float sum = 0.f;
    #pragma unroll
    for (int t = 0; t < K2; t++) { p[t] = __expf(p[t] - m); sum += p[t]; }
    const float inv = 1.f / sum;

    if ((lane & 7) == 0) {
        #pragma unroll
        for (int t = 0; t < K2; t++) sP[warp][head][t] = p[t];
        sInv[warp][head] = inv;
    }

    // Pass B: V accumulation with gather-form coefficients (compile-time pruned).
    const float w00 = wy0*wx0, w01 = wy0*wx1, w10 = wy1*wx0, w11 = wy1*wx1;
    float accx = 0.f, accy = 0.f;
    #pragma unroll
    for (int gy = 0; gy < 6; gy++) {
        int iy = iy_base + gy;
        bool okY = ((unsigned)iy < (unsigned)H);
        int iyc = min(max(iy, 0), H-1);
        #pragma unroll
        for (int gx = 0; gx < 6; gx++) {
            int ix = ix_base + gx;
            bool ok = okY && ((unsigned)ix < (unsigned)WW);
            int ixc = min(max(ix, 0), WW-1);
            float coef = 0.f;
            if (gy < 5 && gx < 5) coef = fmaf(p[gy*5 + gx],       w00, coef);
            if (gy < 5 && gx > 0) coef = fmaf(p[gy*5 + gx-1],     w01, coef);
            if (gy > 0 && gx < 5) coef = fmaf(p[(gy-1)*5 + gx],   w10, coef);
            if (gy > 0 && gx > 0) coef = fmaf(p[(gy-1)*5 + gx-1], w11, coef);
            coef = ok ? coef : 0.f;
            float2 vv = __ldg(&vp2[(batchOff + iyc*WW + ixc)*32 + lane]);
            accx = fmaf(coef, vv.x, accx);
            accy = fmaf(coef, vv.y, accy);
        }
    }

    ((float2*)g_mid)[(size_t)(b*HW + pix)*32 + lane] =
        make_float2(accx*inv, accy*inv);

    __syncthreads();

    // attn map [n, nh, k2, h, w]; 4*25*8 = 800 values per block, pixel-fastest.
    for (int i = tid; i < NH*K2*8; i += 256) {
        int pi = i & 7;
        int ht = i >> 3;
        int hh = ht / K2, t = ht % K2;
        float val = sP[pi][hh][t] * sInv[pi][hh];
        attn_out[((size_t)(b*NH + hh)*K2 + t)*HW + pixBase + pi] = val;
    }
}

// ---------------------------------------------------------------------------
// Kernel 3: final 1x1 conv, g_mid [n,hw,c] -> out [n,c,h,w].
// ---------------------------------------------------------------------------
__global__ __launch_bounds__(256) void conv_out_kernel(const float* __restrict__ Wfc,
                                                       float* __restrict__ out)
{
    __shared__ float Wt[64*66];   // Wt[c][o], pad 66
    __shared__ float O[64*33];    // O[o][pix], pad 33

    const int tid  = threadIdx.x;
    const int warp = tid >> 5;
    const int lane = tid & 31;

    const int pixAll  = blockIdx.x * 32;
    const int b       = pixAll / HW;
    const int pixBase = pixAll % HW;

    for (int i = tid; i < C*C; i += 256)
        Wt[(i & 63)*66 + (i >> 6)] = Wfc[i];
    __syncthreads();

    const float2* __restrict__ mid2 = (const float2*)g_mid;
    const int pixL = warp*4;

    float2 xl[4];
    #pragma unroll
    for (int j = 0; j < 4; j++)
        xl[j] = mid2[(size_t)(b*HW + pixBase + pixL + j)*32 + lane];

    float2 acc[4];
    #pragma unroll
    for (int j = 0; j < 4; j++) acc[j] = make_float2(0.f, 0.f);

    #pragma unroll
    for (int c = 0; c < 64; c++) {
        float2 wv = *(const float2*)&Wt[c*66 + lane*2];
        #pragma unroll
        for (int j = 0; j < 4; j++) {
            float xls = (c & 1) ? xl[j].y : xl[j].x;
            float xc  = __shfl_sync(0xffffffffu, xls, c >> 1);
            acc[j].x = fmaf(wv.x, xc, acc[j].x);
            acc[j].y = fmaf(wv.y, xc, acc[j].y);
        }
    }

    #pragma unroll
    for (int j = 0; j < 4; j++) {
        O[(2*lane    )*33 + pixL + j] = acc[j].x;
        O[(2*lane + 1)*33 + pixL + j] = acc[j].y;
    }
    __syncthreads();

    #pragma unroll
    for (int i = tid; i < C*32; i += 256) {
        int o = i >> 5, pp = i & 31;
        out[(size_t)(b*C + o)*HW + pixBase + pp] = O[o*33 + pp];
    }
}

// ---------------------------------------------------------------------------
extern "C" void kernel_launch(void* const* d_in, const int* in_sizes, int n_in,
                              void* d_out, int out_size)
{
    const float* q    = (const float*)d_in[0];
    const float* k    = (const float*)d_in[1];
    const float* v    = (const float*)d_in[2];
    const float* flow = (const float*)d_in[3];
    const float* Wq   = (const float*)d_in[4];
    const float* Wk   = (const float*)d_in[5];
    const float* Wv   = (const float*)d_in[6];
    const float* Wfc  = (const float*)d_in[7];

    float* out  = (float*)d_out;              // [n, c, h, w]
    float* attn = out + NB*C*HW;              // [n, nh, k2, h, w]

    dim3 g1(NB*HW/128, 3);
    conv_in_kernel<<<g1, 256>>>(q, k, v, Wq, Wk, Wv);
    attn_kernel<<<NB*HW/8, 256>>>(flow, attn);
    conv_out_kernel<<<NB*HW/32, 256>>>(Wfc, out);
}

// round 5
// speedup vs baseline: 1.4964x; 1.4964x over previous
#include <cuda_runtime.h>

#define NB   2
#define C    64
#define H    128
#define WW   128
#define HW   (H*WW)
#define NH   4
#define DK   16
#define KS   5
#define K2   25

// Scratch (allocation-free rule: __device__ globals).
// qp/kp/vp/mid stored pixel-major: [n, h*w, c]  (channel contiguous -> coalesced gathers)
__device__ float g_qp [NB*HW*C];
__device__ float g_kp [NB*HW*C];
__device__ float g_vp [NB*HW*C];
__device__ float g_mid[NB*HW*C];

// ---------------------------------------------------------------------------
// Kernel 1: three 1x1 convs, [n,c,h,w] -> [n,h*w,c] (transposed), register-tiled.
// Block: 256 threads, tile 128 pixels x 64 outs. Thread: 4 pix x 8 outs.
// ---------------------------------------------------------------------------
__global__ __launch_bounds__(256) void conv_in_kernel(
    const float* __restrict__ q,
    const float* __restrict__ k,
    const float* __restrict__ v,
    const float* __restrict__ Wq,
    const float* __restrict__ Wk,
    const float* __restrict__ Wv)
{
    __shared__ float Xs[64*128];

    const int which = blockIdx.y;
    const float* src = (which == 0) ? q  : (which == 1) ? k  : v;
    const float* Wsrc= (which == 0) ? Wq : (which == 1) ? Wk : Wv;
    float*       dst = (which == 0) ? g_qp : (which == 1) ? g_kp : g_vp;

    const int b       = blockIdx.x / (HW/128);
    const int pixBase = (blockIdx.x % (HW/128)) * 128;
    const int tid     = threadIdx.x;

    #pragma unroll
    for (int kx = 0; kx < 8; kx++) {
        int idx4 = tid + kx*256;
        int c  = idx4 >> 5;
        int p4 = idx4 & 31;
        float4 val = __ldg((const float4*)(src + (size_t)(b*C + c)*HW + pixBase + p4*4));
        *(float4*)&Xs[c*128 + p4*4] = val;
    }
    __syncthreads();

    const int tidx = tid & 31;
    const int tidy = tid >> 5;
    const float* Wb = Wsrc + tidy*8*C;

    float acc[4][8];
    #pragma unroll
    for (int j = 0; j < 4; j++)
        #pragma unroll
        for (int i = 0; i < 8; i++) acc[j][i] = 0.f;

    #pragma unroll 4
    for (int c0 = 0; c0 < 64; c0 += 4) {
        float wreg[8][4];
        #pragma unroll
        for (int i = 0; i < 8; i++) {
            float4 t = __ldg((const float4*)(Wb + i*C + c0));
            wreg[i][0] = t.x; wreg[i][1] = t.y; wreg[i][2] = t.z; wreg[i][3] = t.w;
        }
        #pragma unroll
        for (int cc = 0; cc < 4; cc++) {
            #pragma unroll
            for (int j = 0; j < 4; j++) {
                float xv = Xs[(c0+cc)*128 + tidx + 32*j];
                #pragma unroll
                for (int i = 0; i < 8; i++)
                    acc[j][i] = fmaf(wreg[i][cc], xv, acc[j][i]);
            }
        }
    }

    #pragma unroll
    for (int j = 0; j < 4; j++) {
        int pix = pixBase + tidx + 32*j;
        float4 a0 = make_float4(acc[j][0], acc[j][1], acc[j][2], acc[j][3]);
        float4 a1 = make_float4(acc[j][4], acc[j][5], acc[j][6], acc[j][7]);
        float* d = dst + (size_t)(b*HW + pix)*C + tidy*8;
        *(float4*)d       = a0;
        *(float4*)(d + 4) = a1;
    }
}

// ---------------------------------------------------------------------------
// Kernel 2: flow-guided attention. TWO pixels per warp:
//   lanes 0-15 -> pixel A, lanes 16-31 -> pixel B; lane owns 4 channels
//   (float4), 4 lanes per head. 6x6 shared-grid factorization with rolling
//   2-row buffer; gather-form coefficients in pass B. Head reduction = 2 shfl.
// Block: 256 threads = 8 warps = 16 pixels.
// ---------------------------------------------------------------------------
__global__ __launch_bounds__(256) void attn_kernel(const float* __restrict__ flow,
                                                   float* __restrict__ attn_out)
{
    __shared__ float sP[16][NH][K2];
    __shared__ float sInv[16][NH];

    const int tid  = threadIdx.x;
    const int warp = tid >> 5;
    const int lane = tid & 31;
    const int half = lane >> 4;      // which pixel of the pair
    const int sub  = lane & 15;      // channel group: channels 4*sub..4*sub+3

    const int b       = blockIdx.x / (HW/16);
    const int pixBase = (blockIdx.x % (HW/16)) * 16;
    const int lp      = warp*2 + half;          // local pixel 0..15
    const int pix     = pixBase + lp;
    const int y = pix >> 7;
    const int x = pix & 127;

    const float fx = flow[(b*2 + 0)*HW + pix];
    const float fy = flow[(b*2 + 1)*HW + pix];

    const float axf = (float)x + fx;
    const float ayf = (float)y + fy;
    const float x0f = floorf(axf), y0f = floorf(ayf);
    const int ix_base = (int)x0f - 2;
    const int iy_base = (int)y0f - 2;
    const float wx1 = axf - x0f, wx0 = 1.f - wx1;
    const float wy1 = ayf - y0f, wy0 = 1.f - wy1;

    const float4* __restrict__ qp4 = (const float4*)g_qp;
    const float4* __restrict__ kp4 = (const float4*)g_kp;
    const float4* __restrict__ vp4 = (const float4*)g_vp;

    float4 qv = qp4[(size_t)(b*HW + pix)*16 + sub];
    const float scale = 0.25f;              // 1/sqrt(dk=16)
    qv.x *= scale; qv.y *= scale; qv.z *= scale; qv.w *= scale;

    const size_t batchOff = (size_t)b*HW;

    // Precompute clamped column indices + validity (per half-warp uniform).
    int   ixc[6];
    float okX[6];
    #pragma unroll
    for (int dx = 0; dx < 6; dx++) {
        int ix = ix_base + dx;
        okX[dx] = ((unsigned)ix < (unsigned)WW) ? 1.f : 0.f;
        ixc[dx] = min(max(ix, 0), WW-1);
    }

    // Rolling pass A: grid row dy -> srow[dy&1]; after row dy, emit logit row dy-1.
    float p[25];
    float m = -1e30f;
    float srow[2][6];

    #pragma unroll
    for (int dy = 0; dy < 6; dy++) {
        const int cur = dy & 1;
        int iy = iy_base + dy;
        float okY = ((unsigned)iy < (unsigned)H) ? 1.f : 0.f;
        int iyc = min(max(iy, 0), H-1);
        const size_t rowOff = batchOff + (size_t)iyc*WW;
        #pragma unroll
        for (int dx = 0; dx < 6; dx++) {
            float4 kv = __ldg(&kp4[(rowOff + ixc[dx])*16 + sub]);
            float d = qv.x*kv.x + qv.y*kv.y + qv.z*kv.z + qv.w*kv.w;
            d += __shfl_xor_sync(0xffffffffu, d, 1);
            d += __shfl_xor_sync(0xffffffffu, d, 2);
            srow[cur][dx] = d * (okY * okX[dx]);
        }
        if (dy > 0) {
            const int prv = cur ^ 1;
            #pragma unroll
            for (int tx = 0; tx < 5; tx++) {
                float l = wy0 * fmaf(wx0, srow[prv][tx], wx1 * srow[prv][tx+1])
                        + wy1 * fmaf(wx0, srow[cur][tx], wx1 * srow[cur][tx+1]);
                p[(dy-1)*5 + tx] = l;
                m = fmaxf(m, l);
            }
        }
    }

    float sum = 0.f;
    #pragma unroll
    for (int t = 0; t < K2; t++) { p[t] = __expf(p[t] - m); sum += p[t]; }
    const float inv = 1.f / sum;

    if ((lane & 3) == 0) {
        const int head = sub >> 2;
        #pragma unroll
        for (int t = 0; t < K2; t++) sP[lp][head][t] = p[t];
        sInv[lp][head] = inv;
    }

    // Pass B: V accumulation with gather-form coefficients (compile-time pruned).
    const float w00 = wy0*wx0, w01 = wy0*wx1, w10 = wy1*wx0, w11 = wy1*wx1;
    float4 acc = make_float4(0.f, 0.f, 0.f, 0.f);
    #pragma unroll
    for (int gy = 0; gy < 6; gy++) {
        int iy = iy_base + gy;
        float okY = ((unsigned)iy < (unsigned)H) ? 1.f : 0.f;
        int iyc = min(max(iy, 0), H-1);
        const size_t rowOff = batchOff + (size_t)iyc*WW;
        #pragma unroll
        for (int gx = 0; gx < 6; gx++) {
            float coef = 0.f;
            if (gy < 5 && gx < 5) coef = fmaf(p[gy*5 + gx],       w00, coef);
            if (gy < 5 && gx > 0) coef = fmaf(p[gy*5 + gx-1],     w01, coef);
            if (gy > 0 && gx < 5) coef = fmaf(p[(gy-1)*5 + gx],   w10, coef);
            if (gy > 0 && gx > 0) coef = fmaf(p[(gy-1)*5 + gx-1], w11, coef);
            coef *= okY * okX[gx];
            float4 vv = __ldg(&vp4[(rowOff + ixc[gx])*16 + sub]);
            acc.x = fmaf(coef, vv.x, acc.x);
            acc.y = fmaf(coef, vv.y, acc.y);
            acc.z = fmaf(coef, vv.z, acc.z);
            acc.w = fmaf(coef, vv.w, acc.w);
        }
    }

    acc.x *= inv; acc.y *= inv; acc.z *= inv; acc.w *= inv;
    ((float4*)g_mid)[(size_t)(b*HW + pix)*16 + sub] = acc;

    __syncthreads();

    // attn map [n, nh, k2, h, w]; 4*25*16 = 1600 values per block, pixel-fastest.
    for (int i = tid; i < NH*K2*16; i += 256) {
        int pi = i & 15;
        int ht = i >> 4;
        int hh = ht / K2, t = ht % K2;
        float val = sP[pi][hh][t] * sInv[pi][hh];
        attn_out[((size_t)(b*NH + hh)*K2 + t)*HW + pixBase + pi] = val;
    }
}

// ---------------------------------------------------------------------------
// Kernel 3: final 1x1 conv, g_mid [n,hw,c] -> out [n,c,h,w].
// Block: 256 threads = 8 warps x 8 pixels = 64 pixels. Lane owns 2 out chans,
// x broadcast via shuffle; W transposed in smem; output transposed via smem.
// ---------------------------------------------------------------------------
__global__ __launch_bounds__(256) void conv_out_kernel(const float* __restrict__ Wfc,
                                                       float* __restrict__ out)
{
    __shared__ float Wt[64*66];   // Wt[c][o], pad 66
    __shared__ float O[64*65];    // O[o][pix], pad 65

    const int tid  = threadIdx.x;
    const int warp = tid >> 5;
    const int lane = tid & 31;

    const int pixAll  = blockIdx.x * 64;
    const int b       = pixAll / HW;
    const int pixBase = pixAll % HW;

    for (int i = tid; i < C*C; i += 256)
        Wt[(i & 63)*66 + (i >> 6)] = Wfc[i];
    __syncthreads();

    const float2* __restrict__ mid2 = (const float2*)g_mid;
    const int pixL = warp*8;

    float2 xl[8];
    #pragma unroll
    for (int j = 0; j < 8; j++)
        xl[j] = mid2[(size_t)(b*HW + pixBase + pixL + j)*32 + lane];

    float2 acc[8];
    #pragma unroll
    for (int j = 0; j < 8; j++) acc[j] = make_float2(0.f, 0.f);

    #pragma unroll
    for (int c = 0; c < 64; c++) {
        float2 wv = *(const float2*)&Wt[c*66 + lane*2];
        #pragma unroll
        for (int j = 0; j < 8; j++) {
            float xls = (c & 1) ? xl[j].y : xl[j].x;
            float xc  = __shfl_sync(0xffffffffu, xls, c >> 1);
            acc[j].x = fmaf(wv.x, xc, acc[j].x);
            acc[j].y = fmaf(wv.y, xc, acc[j].y);
        }
    }

    #pragma unroll
    for (int j = 0; j < 8; j++) {
        O[(2*lane    )*65 + pixL + j] = acc[j].x;
        O[(2*lane + 1)*65 + pixL + j] = acc[j].y;
    }
    __syncthreads();

    #pragma unroll
    for (int i = tid; i < C*64; i += 256) {
        int o = i >> 6, pp = i & 63;
        out[(size_t)(b*C + o)*HW + pixBase + pp] = O[o*65 + pp];
    }
}

// ---------------------------------------------------------------------------
extern "C" void kernel_launch(void* const* d_in, const int* in_sizes, int n_in,
                              void* d_out, int out_size)
{
    const float* q    = (const float*)d_in[0];
    const float* k    = (const float*)d_in[1];
    const float* v    = (const float*)d_in[2];
    const float* flow = (const float*)d_in[3];
    const float* Wq   = (const float*)d_in[4];
    const float* Wk   = (const float*)d_in[5];
    const float* Wv   = (const float*)d_in[6];
    const float* Wfc  = (const float*)d_in[7];

    float* out  = (float*)d_out;              // [n, c, h, w]
    float* attn = out + NB*C*HW;              // [n, nh, k2, h, w]

    dim3 g1(NB*HW/128, 3);
    conv_in_kernel<<<g1, 256>>>(q, k, v, Wq, Wk, Wv);
    attn_kernel<<<NB*HW/16, 256>>>(flow, attn);
    conv_out_kernel<<<NB*HW/64, 256>>>(Wfc, out);
}